// round 16
// baseline (speedup 1.0000x reference)
#include <cuda_runtime.h>
#include <math.h>
#include <stdint.h>

#define D_MODEL 512
#define BATCH   4
#define SEQ     2048
#define TOK     (BATCH * SEQ)   // 8192

// ---- scratch (allocation-free: static device globals) ----
// "pair" arrays hold tf32-split values interleaved: [2i]=hi, [2i+1]=lo
__device__ float g_x2[2 * TOK * D_MODEL];                // 32 MiB
__device__ float g_w2[2 * 4 * D_MODEL * D_MODEL];        // 8 MiB  (Wq|Wk|Wv|Wo)
__device__ float g_qkv2[2 * 3 * TOK * D_MODEL];          // 96 MiB (Q|K|V)
__device__ float g_s[(size_t)BATCH * SEQ * SEQ];         // 64 MiB (scores fp32)
__device__ float g_p2[2 * (size_t)BATCH * SEQ * SEQ];    // 128 MiB (softmax out)
__device__ float g_att2[2 * TOK * D_MODEL];              // 32 MiB

// ---- PTX helpers ----
__device__ __forceinline__ void cp_async16(uint32_t dst_smem, const void* src) {
    asm volatile("cp.async.cg.shared.global [%0], [%1], 16;\n"
                 :: "r"(dst_smem), "l"(src) : "memory");
}
__device__ __forceinline__ void cp_commit() {
    asm volatile("cp.async.commit_group;\n" ::: "memory");
}
__device__ __forceinline__ void cp_wait0() {
    asm volatile("cp.async.wait_group 0;\n" ::: "memory");
}
__device__ __forceinline__ uint32_t to_tf32(float x) {
    uint32_t r;
    asm("cvt.rna.tf32.f32 %0, %1;" : "=r"(r) : "f"(x));
    return r;
}
// 3xTF32 split: x ~= hi + lo, both tf32-valued fp32
__device__ __forceinline__ void tf32_split_f(float x, float& hi, float& lo) {
    hi = __uint_as_float(to_tf32(x));
    lo = __uint_as_float(to_tf32(x - hi));
}
// m16n8k8 tf32 MMA: A 4 regs, B 2 regs, C 4 fp32
__device__ __forceinline__ void mma_tf32_k8(float acc[4], const uint32_t a[4],
                                            const uint32_t b[2]) {
    asm volatile(
        "mma.sync.aligned.m16n8k8.row.col.f32.tf32.tf32.f32 "
        "{%0,%1,%2,%3}, {%4,%5,%6,%7}, {%8,%9}, {%0,%1,%2,%3};\n"
        : "+f"(acc[0]), "+f"(acc[1]), "+f"(acc[2]), "+f"(acc[3])
        : "r"(a[0]), "r"(a[1]), "r"(a[2]), "r"(a[3]), "r"(b[0]), "r"(b[1]));
}

// ============================================================================
// Elementwise tf32 splitter -> interleaved pairs. n4 = element count / 4.
// ============================================================================
__global__ __launch_bounds__(256)
void split2_kernel(const float* __restrict__ in, float* __restrict__ pair, int n4)
{
    const int i = blockIdx.x * 256 + threadIdx.x;
    if (i >= n4) return;
    float4 v = ((const float4*)in)[i];
    float4 h, l;
    tf32_split_f(v.x, h.x, l.x);
    tf32_split_f(v.y, h.y, l.y);
    tf32_split_f(v.z, h.z, l.z);
    tf32_split_f(v.w, h.w, l.w);
    ((float4*)pair)[2 * i + 0] = make_float4(h.x, l.x, h.y, l.y);
    ((float4*)pair)[2 * i + 1] = make_float4(h.z, l.z, h.w, l.w);
}

// ============================================================================
// 3xTF32 tensor-core GEMM body, PRE-SPLIT interleaved (hi,lo)-pair operands.
// Mainloop: 24 LDS.64 + 48 MMA per k8-chunk — no cvt/sub, half the LDS count.
//   TRANSB = true :  C[m][n] = scale * sum_k A[m][k] * B[n][k]  (+ bias[n])
//   TRANSB = false:  C[m][n] = scale * sum_k A[m][k] * B[k][n]  (+ bias[n])
// SPLITC: epilogue writes interleaved split pairs into C (pair array).
// BM=BN=128, BK=16, 256 threads = 8 warps (2x4). Warp tile 64x32.
// Numerically identical to the round-9 kernel (same splits, same MMA order).
// Ap/Bp index in PAIRS (float2); strides in pairs.
// ============================================================================
template <bool TRANSB, bool BIAS, bool SPLITC>
__device__ __forceinline__
void gemm_tc_body(const float2* __restrict__ Ap, const float2* __restrict__ Bp,
                  const float* __restrict__ bias, float* __restrict__ C,
                  int Nn, int K, float scale)
{
    constexpr int BM = 128, BK = 16;
    constexpr int AS_P = 20;     // pairs per A row   (LDS.64 conflict-free)
    constexpr int BT_P = 20;     // pairs per Bs row (TRANSB)
    constexpr int BN_P = 132;    // pairs per Bs row (NN)
    constexpr int A_BUF = BM * AS_P;                         // 2560 pairs
    constexpr int B_BUF = TRANSB ? (BM * BT_P) : (BK * BN_P); // 2560 | 2112

    extern __shared__ float2 smem2[];
    float2* A_s = smem2;                 // [2][A_BUF]
    float2* B_s = smem2 + 2 * A_BUF;     // [2][B_BUF]

    const int tid  = threadIdx.x;
    const int wid  = tid >> 5;
    const int lane = tid & 31;
    const int g    = lane >> 2;
    const int c    = lane & 3;
    const int wm   = wid >> 2;
    const int wn   = wid & 3;

    const int m0 = blockIdx.y * BM;
    const int n0 = blockIdx.x * BM;

    float acc[4][4][4];
#pragma unroll
    for (int mt = 0; mt < 4; mt++)
#pragma unroll
        for (int nt = 0; nt < 4; nt++)
#pragma unroll
            for (int r = 0; r < 4; r++) acc[mt][nt][r] = 0.0f;

    const uint32_t a_sm = (uint32_t)__cvta_generic_to_shared(A_s);
    const uint32_t b_sm = (uint32_t)__cvta_generic_to_shared(B_s);

    // ---- tile copy: 1024 16B-chunks (2 pairs each) for A and B, 4/thread ----
    auto copy_tile = [&](int k0, int buf) {
#pragma unroll
        for (int i = 0; i < 4; i++) {                 // A: [BM][BK] pairs
            const int chunk = tid + i * 256;          // 0..1023
            const int row = chunk >> 3;               // 8 chunks per row
            const int pc  = (chunk & 7) << 1;         // pair index 0..14
            cp_async16(a_sm + (uint32_t)(buf * A_BUF + row * AS_P + pc) * 8,
                       &Ap[(size_t)(m0 + row) * K + k0 + pc]);
        }
        if (TRANSB) {
#pragma unroll
            for (int i = 0; i < 4; i++) {             // B: [BN][BK] pairs
                const int chunk = tid + i * 256;
                const int row = chunk >> 3;
                const int pc  = (chunk & 7) << 1;
                cp_async16(b_sm + (uint32_t)(buf * B_BUF + row * BT_P + pc) * 8,
                           &Bp[(size_t)(n0 + row) * K + k0 + pc]);
            }
        } else {
#pragma unroll
            for (int i = 0; i < 4; i++) {             // B: [BK][BN] pairs
                const int chunk = tid + i * 256;
                const int row = chunk >> 6;           // 64 chunks per row
                const int pc  = (chunk & 63) << 1;
                cp_async16(b_sm + (uint32_t)(buf * B_BUF + row * BN_P + pc) * 8,
                           &Bp[(size_t)(k0 + row) * Nn + n0 + pc]);
            }
        }
    };

    copy_tile(0, 0);
    cp_commit();

    const int ksteps = K / BK;
    int buf = 0;
    for (int step = 0; step < ksteps; step++) {
        cp_wait0();
        __syncthreads();
        if (step + 1 < ksteps) {
            copy_tile((step + 1) * BK, buf ^ 1);
            cp_commit();
        }

        const uint2* Aw = (const uint2*)(A_s + buf * A_BUF);
        const uint2* Bw = (const uint2*)(B_s + buf * B_BUF);

#pragma unroll
        for (int kc = 0; kc < 2; kc++) {
            const int col0 = kc * 8 + c;
            const int col1 = col0 + 4;

            uint32_t afh[4][4], afl[4][4];
#pragma unroll
            for (int mt = 0; mt < 4; mt++) {
                const int r0 = wm * 64 + mt * 16 + g;
                uint2 p;
                p = Aw[(r0    ) * AS_P + col0]; afh[mt][0] = p.x; afl[mt][0] = p.y;
                p = Aw[(r0 + 8) * AS_P + col0]; afh[mt][1] = p.x; afl[mt][1] = p.y;
                p = Aw[(r0    ) * AS_P + col1]; afh[mt][2] = p.x; afl[mt][2] = p.y;
                p = Aw[(r0 + 8) * AS_P + col1]; afh[mt][3] = p.x; afl[mt][3] = p.y;
            }
            uint32_t bfh[4][2], bfl[4][2];
#pragma unroll
            for (int nt = 0; nt < 4; nt++) {
                const int nn = wn * 32 + nt * 8 + g;
                uint2 p;
                if (TRANSB) {
                    p = Bw[nn * BT_P + col0]; bfh[nt][0] = p.x; bfl[nt][0] = p.y;
                    p = Bw[nn * BT_P + col1]; bfh[nt][1] = p.x; bfl[nt][1] = p.y;
                } else {
                    p = Bw[col0 * BN_P + nn]; bfh[nt][0] = p.x; bfl[nt][0] = p.y;
                    p = Bw[col1 * BN_P + nn]; bfh[nt][1] = p.x; bfl[nt][1] = p.y;
                }
            }

            // term-outermost; per-accumulator order ll-cross -> hl -> hh
#pragma unroll
            for (int mt = 0; mt < 4; mt++)
#pragma unroll
                for (int nt = 0; nt < 4; nt++)
                    mma_tf32_k8(acc[mt][nt], afl[mt], bfh[nt]);
#pragma unroll
            for (int mt = 0; mt < 4; mt++)
#pragma unroll
                for (int nt = 0; nt < 4; nt++)
                    mma_tf32_k8(acc[mt][nt], afh[mt], bfl[nt]);
#pragma unroll
            for (int mt = 0; mt < 4; mt++)
#pragma unroll
                for (int nt = 0; nt < 4; nt++)
                    mma_tf32_k8(acc[mt][nt], afh[mt], bfh[nt]);
        }
        buf ^= 1;
    }

    // ---- epilogue ----
#pragma unroll
    for (int nt = 0; nt < 4; nt++) {
        const int colb = n0 + wn * 32 + nt * 8 + c * 2;
        float2 bv = make_float2(0.0f, 0.0f);
        if (BIAS) { bv.x = bias[colb]; bv.y = bias[colb + 1]; }
#pragma unroll
        for (int mt = 0; mt < 4; mt++) {
            const int r0 = m0 + wm * 64 + mt * 16 + g;
#pragma unroll
            for (int h = 0; h < 2; h++) {
                const float v0 = fmaf(acc[mt][nt][h * 2 + 0], scale, bv.x);
                const float v1 = fmaf(acc[mt][nt][h * 2 + 1], scale, bv.y);
                const size_t off = (size_t)(r0 + h * 8) * Nn + colb;
                if (SPLITC) {
                    float h0, l0, h1, l1;
                    tf32_split_f(v0, h0, l0);
                    tf32_split_f(v1, h1, l1);
                    *(float4*)&C[2 * off] = make_float4(h0, l0, h1, l1);
                } else {
                    *(float2*)&C[off] = make_float2(v0, v1);
                }
            }
        }
    }
}

// Generic batched wrapper (blockIdx.z strides over batch; strides in pairs/elems)
template <bool TRANSB, bool BIAS, bool SPLITC>
__global__ __launch_bounds__(256, 2)
void gemm_tc(const float2* __restrict__ Ap, const float2* __restrict__ Bp,
             const float* __restrict__ bias, float* __restrict__ C,
             int Nn, int K, float scale, size_t sA, size_t sB, size_t sC)
{
    gemm_tc_body<TRANSB, BIAS, SPLITC>(Ap + (size_t)blockIdx.z * sA,
                                       Bp + (size_t)blockIdx.z * sB,
                                       bias,
                                       C + (size_t)blockIdx.z * sC * (SPLITC ? 2 : 1),
                                       Nn, K, scale);
}

// Fused Q/K/V projection: blockIdx.z in {0,1,2} selects weights/bias/output.
__global__ __launch_bounds__(256, 2)
void gemm_proj3(const float2* __restrict__ xp, const float2* __restrict__ wp,
                const float* __restrict__ bq, const float* __restrict__ bk,
                const float* __restrict__ bv, float* __restrict__ qkvp)
{
    const int z = blockIdx.z;
    const float* b = (z == 0) ? bq : (z == 1) ? bk : bv;
    gemm_tc_body<true, true, true>(xp, wp + (size_t)z * D_MODEL * D_MODEL, b,
                                   qkvp + 2 * (size_t)z * TOK * D_MODEL,
                                   D_MODEL, D_MODEL, 1.0f);
}

// ============================================================================
// Row softmax: fp32 scores in, interleaved tf32-split pairs out.
// One block (256 threads) per row of length SEQ.
// ============================================================================
__global__ __launch_bounds__(256)
void softmax_kernel(const float* __restrict__ S, float* __restrict__ P)
{
    const size_t base = blockIdx.x * (size_t)SEQ;
    const float4* p4 = (const float4*)(S + base);
    const int tid = threadIdx.x;
    const int lane = tid & 31;
    const int wid = tid >> 5;

    float4 v0 = p4[tid];
    float4 v1 = p4[tid + 256];

    float m = fmaxf(fmaxf(fmaxf(v0.x, v0.y), fmaxf(v0.z, v0.w)),
                    fmaxf(fmaxf(v1.x, v1.y), fmaxf(v1.z, v1.w)));
#pragma unroll
    for (int off = 16; off > 0; off >>= 1)
        m = fmaxf(m, __shfl_xor_sync(0xFFFFFFFFu, m, off));

    __shared__ float red[8];
    if (lane == 0) red[wid] = m;
    __syncthreads();
    m = red[0];
#pragma unroll
    for (int w = 1; w < 8; w++) m = fmaxf(m, red[w]);
    __syncthreads();

    v0.x = __expf(v0.x - m); v0.y = __expf(v0.y - m);
    v0.z = __expf(v0.z - m); v0.w = __expf(v0.w - m);
    v1.x = __expf(v1.x - m); v1.y = __expf(v1.y - m);
    v1.z = __expf(v1.z - m); v1.w = __expf(v1.w - m);

    float s = (v0.x + v0.y + v0.z + v0.w) + (v1.x + v1.y + v1.z + v1.w);
#pragma unroll
    for (int off = 16; off > 0; off >>= 1)
        s += __shfl_xor_sync(0xFFFFFFFFu, s, off);

    __shared__ float reds[8];
    if (lane == 0) reds[wid] = s;
    __syncthreads();
    s = reds[0];
#pragma unroll
    for (int w = 1; w < 8; w++) s += reds[w];

    const float inv = 1.0f / s;
    v0.x *= inv; v0.y *= inv; v0.z *= inv; v0.w *= inv;
    v1.x *= inv; v1.y *= inv; v1.z *= inv; v1.w *= inv;

    float4 h0, l0, h1, l1;
    tf32_split_f(v0.x, h0.x, l0.x); tf32_split_f(v0.y, h0.y, l0.y);
    tf32_split_f(v0.z, h0.z, l0.z); tf32_split_f(v0.w, h0.w, l0.w);
    tf32_split_f(v1.x, h1.x, l1.x); tf32_split_f(v1.y, h1.y, l1.y);
    tf32_split_f(v1.z, h1.z, l1.z); tf32_split_f(v1.w, h1.w, l1.w);

    float4* out = (float4*)(P + 2 * base);
    out[2 * tid + 0]         = make_float4(h0.x, l0.x, h0.y, l0.y);
    out[2 * tid + 1]         = make_float4(h0.z, l0.z, h0.w, l0.w);
    out[2 * (tid + 256) + 0] = make_float4(h1.x, l1.x, h1.y, l1.y);
    out[2 * (tid + 256) + 1] = make_float4(h1.z, l1.z, h1.w, l1.w);
}

// ============================================================================
// Launch
// ============================================================================
extern "C" void kernel_launch(void* const* d_in, const int* in_sizes, int n_in,
                              void* d_out, int out_size)
{
    (void)in_sizes; (void)n_in; (void)out_size;
    const float* x  = (const float*)d_in[0];
    const float* Wq = (const float*)d_in[1];
    const float* bq = (const float*)d_in[2];
    const float* Wk = (const float*)d_in[3];
    const float* bk = (const float*)d_in[4];
    const float* Wv = (const float*)d_in[5];
    const float* bv = (const float*)d_in[6];
    const float* Wo = (const float*)d_in[7];
    const float* bo = (const float*)d_in[8];
    float* out = (float*)d_out;

    float *xp, *wp, *qkvp, *sp, *pp, *atp;
    cudaGetSymbolAddress((void**)&xp,   g_x2);
    cudaGetSymbolAddress((void**)&wp,   g_w2);
    cudaGetSymbolAddress((void**)&qkvp, g_qkv2);
    cudaGetSymbolAddress((void**)&sp,   g_s);
    cudaGetSymbolAddress((void**)&pp,   g_p2);
    cudaGetSymbolAddress((void**)&atp,  g_att2);

    // dynamic smem (bytes): (A_BUF + B_BUF) pairs * 2 buffers * 8B
    const int SM_T = (2 * 2560 + 2 * 2560) * 8;   // TRANSB: 81920
    const int SM_N = (2 * 2560 + 2 * 2112) * 8;   // NN:     74752
    cudaFuncSetAttribute(gemm_proj3, cudaFuncAttributeMaxDynamicSharedMemorySize, SM_T);
    cudaFuncSetAttribute(gemm_tc<true, false, false>, cudaFuncAttributeMaxDynamicSharedMemorySize, SM_T);
    cudaFuncSetAttribute(gemm_tc<false, false, true>, cudaFuncAttributeMaxDynamicSharedMemorySize, SM_N);
    cudaFuncSetAttribute(gemm_tc<true, true, false>,  cudaFuncAttributeMaxDynamicSharedMemorySize, SM_T);

    const dim3 blk(256);
    const float inv_sqrt_d = 0.04419417382415922f;   // 1/sqrt(512)
    const int NW = D_MODEL * D_MODEL;                // 262144

    // ---- split inputs into interleaved pair arrays ----
    split2_kernel<<<(TOK * D_MODEL / 4 + 255) / 256, blk>>>(x, xp, TOK * D_MODEL / 4);
    split2_kernel<<<(NW / 4 + 255) / 256, blk>>>(Wq, wp + 0, NW / 4);
    split2_kernel<<<(NW / 4 + 255) / 256, blk>>>(Wk, wp + 2 * (size_t)NW, NW / 4);
    split2_kernel<<<(NW / 4 + 255) / 256, blk>>>(Wv, wp + 4 * (size_t)NW, NW / 4);
    split2_kernel<<<(NW / 4 + 255) / 256, blk>>>(Wo, wp + 6 * (size_t)NW, NW / 4);

    // ---- fused Q/K/V projections (split pair output) ----
    const dim3 gp3(D_MODEL / 128, TOK / 128, 3);     // 768 CTAs
    gemm_proj3<<<gp3, blk, SM_T>>>((const float2*)xp, (const float2*)wp,
                                   bq, bk, bv, qkvp);

    const float2* qp2 = (const float2*)qkvp;
    const float2* kp2 = (const float2*)qkvp + (size_t)TOK * D_MODEL;
    const float2* vp2 = (const float2*)qkvp + 2 * (size_t)TOK * D_MODEL;

    // ---- scores: per batch [2048,2048] = Q @ K^T * scale (fp32 out) ----
    const dim3 gsc(SEQ / 128, SEQ / 128, BATCH);
    gemm_tc<true, false, false><<<gsc, blk, SM_T>>>(qp2, kp2, nullptr, sp,
                                                    SEQ, D_MODEL, inv_sqrt_d,
                                                    (size_t)SEQ * D_MODEL,
                                                    (size_t)SEQ * D_MODEL,
                                                    (size_t)SEQ * SEQ);

    // ---- softmax (split pair output) ----
    softmax_kernel<<<TOK, blk>>>(sp, pp);

    // ---- att: per batch [2048,512] = P @ V (split pair output) ----
    const dim3 gav(D_MODEL / 128, SEQ / 128, BATCH);
    gemm_tc<false, false, true><<<gav, blk, SM_N>>>((const float2*)pp, vp2,
                                                    nullptr, atp,
                                                    D_MODEL, SEQ, 1.0f,
                                                    (size_t)SEQ * SEQ,
                                                    (size_t)SEQ * D_MODEL,
                                                    (size_t)SEQ * D_MODEL);

    // ---- output projection: [8192,512] = att @ Wo^T + bo (fp32 out) ----
    const dim3 gproj(D_MODEL / 128, TOK / 128, 1);
    gemm_tc<true, true, false><<<gproj, blk, SM_T>>>((const float2*)atp,
                                                     (const float2*)wp + 3 * (size_t)NW,
                                                     bo, out,
                                                     D_MODEL, D_MODEL, 1.0f, 0, 0, 0);
}